// round 1
// baseline (speedup 1.0000x reference)
#include <cuda_runtime.h>

// Problem dims (fixed for this problem instance)
#define B_  2048
#define T_  512
#define I_  58      // input features
#define H_  23      // hidden
#define G_  69      // 3*H gate rows
#define GP_ 72      // padded gate dim (even, 8B-aligned pairs)
#define KP_ 64      // padded K for tf32 mma (8 k-frags of 8)

// Scratch for x-projection: [T][B][GP_] fp32  (~302 MB, static device array — no allocs)
__device__ float g_xg[(size_t)T_ * B_ * GP_];

// ---------------------------------------------------------------------------
// Helpers
// ---------------------------------------------------------------------------
__device__ __forceinline__ unsigned cvt_tf32(float f) {
    unsigned u;
    asm("cvt.rna.tf32.f32 %0, %1;" : "=r"(u) : "f"(f));
    return u;
}

__device__ __forceinline__ unsigned long long pack2(float lo, float hi) {
    unsigned long long r;
    asm("mov.b64 %0, {%1, %2};" : "=l"(r) : "f"(lo), "f"(hi));
    return r;
}
__device__ __forceinline__ void unpack2(unsigned long long v, float& lo, float& hi) {
    asm("mov.b64 {%0, %1}, %2;" : "=f"(lo), "=f"(hi) : "l"(v));
}
// Packed dual-FMA (Blackwell f32x2): d = a*b + c on two lanes at once
__device__ __forceinline__ unsigned long long ffma2(unsigned long long a,
                                                    unsigned long long b,
                                                    unsigned long long c) {
    unsigned long long d;
    asm("fma.rn.f32x2 %0, %1, %2, %3;" : "=l"(d) : "l"(a), "l"(b), "l"(c));
    return d;
}

// Accurate fast sigmoid/tanh via MUFU.EX2 + MUFU.RCP (~1e-7 rel err)
__device__ __forceinline__ float fast_sigmoid(float x) {
    float e, r;
    asm("ex2.approx.f32 %0, %1;" : "=f"(e) : "f"(x * -1.4426950408889634f));
    asm("rcp.approx.f32 %0, %1;" : "=f"(r) : "f"(e + 1.0f));
    return r;
}
__device__ __forceinline__ float fast_tanh(float x) {
    float e, r;
    asm("ex2.approx.f32 %0, %1;" : "=f"(e) : "f"(x * -2.8853900817779268f));
    asm("rcp.approx.f32 %0, %1;" : "=f"(r) : "f"(e + 1.0f));
    return fmaf(2.0f, r, -1.0f);
}

// ---------------------------------------------------------------------------
// Kernel 1: x-projection GEMM (tf32 mma.sync), xg[t][b][g] = task[b][t]·W_ih^T + b_ih
//   Block: 256 threads (8 warps). Each warp computes a 32x72 output tile over K=64.
//   A fragments loaded straight from global (L1-resident per block), B staged in smem.
// ---------------------------------------------------------------------------
__global__ void __launch_bounds__(256, 2)
xproj_kernel(const float* __restrict__ task,
             const float* __restrict__ Wih,
             const float* __restrict__ bih)
{
    __shared__ unsigned Bsh[KP_][GP_];   // tf32 bits: Bsh[k][n] = Wih[n][k]
    __shared__ float    bias[GP_];

    const int tid = threadIdx.x;

    // Stage B (transposed, converted, zero-padded) + bias
    for (int idx = tid; idx < KP_ * GP_; idx += 256) {
        int k = idx / GP_, n = idx % GP_;
        float v = (k < I_ && n < G_) ? Wih[n * I_ + k] : 0.0f;
        Bsh[k][n] = cvt_tf32(v);
    }
    if (tid < GP_) bias[tid] = (tid < G_) ? bih[tid] : 0.0f;
    __syncthreads();

    const int warp = tid >> 5;
    const int lane = tid & 31;
    const int qr = lane >> 2;   // groupID  (0..7)
    const int qc = lane & 3;    // tid-in-group (0..3)
    const int m_warp = blockIdx.x * 256 + warp * 32;

    float acc[2][9][4];
#pragma unroll
    for (int mt = 0; mt < 2; mt++)
#pragma unroll
        for (int nt = 0; nt < 9; nt++)
#pragma unroll
            for (int i = 0; i < 4; i++) acc[mt][nt][i] = 0.0f;

#pragma unroll
    for (int kf = 0; kf < 8; kf++) {
        const int k0 = kf * 8;
        unsigned bfr[9][2];
#pragma unroll
        for (int nt = 0; nt < 9; nt++) {
            bfr[nt][0] = Bsh[k0 + qc][nt * 8 + qr];
            bfr[nt][1] = Bsh[k0 + qc + 4][nt * 8 + qr];
        }
        const int c0 = k0 + qc;
        const int c1 = c0 + 4;
#pragma unroll
        for (int mt = 0; mt < 2; mt++) {
            const float* arow0 = task + (size_t)(m_warp + mt * 16 + qr) * I_;
            const float* arow1 = arow0 + (size_t)8 * I_;
            unsigned a0 = (c0 < I_) ? cvt_tf32(__ldg(arow0 + c0)) : 0u;
            unsigned a1 = (c0 < I_) ? cvt_tf32(__ldg(arow1 + c0)) : 0u;
            unsigned a2 = (c1 < I_) ? cvt_tf32(__ldg(arow0 + c1)) : 0u;
            unsigned a3 = (c1 < I_) ? cvt_tf32(__ldg(arow1 + c1)) : 0u;
#pragma unroll
            for (int nt = 0; nt < 9; nt++) {
                asm volatile(
                    "mma.sync.aligned.m16n8k8.row.col.f32.tf32.tf32.f32 "
                    "{%0,%1,%2,%3}, {%4,%5,%6,%7}, {%8,%9}, {%0,%1,%2,%3};"
                    : "+f"(acc[mt][nt][0]), "+f"(acc[mt][nt][1]),
                      "+f"(acc[mt][nt][2]), "+f"(acc[mt][nt][3])
                    : "r"(a0), "r"(a1), "r"(a2), "r"(a3),
                      "r"(bfr[nt][0]), "r"(bfr[nt][1]));
            }
        }
    }

    // Epilogue: add bias, scatter to xg[t][b][n] (m = b*T + t)
#pragma unroll
    for (int mt = 0; mt < 2; mt++) {
#pragma unroll
        for (int half = 0; half < 2; half++) {
            const int m = m_warp + mt * 16 + qr + half * 8;
            const int b = m >> 9;         // / T_
            const int t = m & (T_ - 1);   // % T_
            float* orow = g_xg + ((size_t)t * B_ + b) * GP_;
#pragma unroll
            for (int nt = 0; nt < 9; nt++) {
                const int n = nt * 8 + qc * 2;
                float2 v;
                v.x = acc[mt][nt][half * 2 + 0] + bias[n];
                v.y = acc[mt][nt][half * 2 + 1] + bias[n + 1];
                *reinterpret_cast<float2*>(orow + n) = v;
            }
        }
    }
}

// ---------------------------------------------------------------------------
// Kernel 2: GRU scan. One warp per batch (2048 warps). Lane l<23 owns unit l.
//   W_hh rows (l, 23+l, 46+l) live in registers as f32x2 pairs over j.
//   h replicated via per-warp smem round-trip each step; matvec in fma.rn.f32x2.
// ---------------------------------------------------------------------------
__global__ void __launch_bounds__(128)
scan_kernel(const float* __restrict__ Whh,
            const float* __restrict__ bhh,
            const float* __restrict__ piw_g,
            const float* __restrict__ pib_g,
            float* __restrict__ out)
{
    const int lane  = threadIdx.x & 31;
    const int wb    = threadIdx.x >> 5;           // warp in block (4 per block)
    const int batch = blockIdx.x * 4 + wb;
    const bool act  = lane < H_;
    const int l     = act ? lane : 0;

    __shared__ __align__(8) float hsh[4][24];

    // Pack W_hh rows for this lane: pairs over j (j=23 padded with 0)
    unsigned long long wr[12], wz[12], wn[12];
#pragma unroll
    for (int j = 0; j < 12; j++) {
        const int j0 = 2 * j, j1 = 2 * j + 1;
        float r1 = (j1 < H_) ? Whh[(size_t)l * H_ + j1] : 0.0f;
        float z1 = (j1 < H_) ? Whh[(size_t)(H_ + l) * H_ + j1] : 0.0f;
        float n1 = (j1 < H_) ? Whh[(size_t)(2 * H_ + l) * H_ + j1] : 0.0f;
        wr[j] = pack2(Whh[(size_t)l * H_ + j0], r1);
        wz[j] = pack2(Whh[(size_t)(H_ + l) * H_ + j0], z1);
        wn[j] = pack2(Whh[(size_t)(2 * H_ + l) * H_ + j0], n1);
    }
    const float bhr = bhh[l], bhz = bhh[H_ + l], bhn = bhh[2 * H_ + l];
    const float piw = piw_g[l], pib = pib_g[l];

    unsigned long long h2[12];
#pragma unroll
    for (int j = 0; j < 12; j++) h2[j] = 0ull;
    float hmine = 0.0f;
    if (lane < 24) hsh[wb][lane] = 0.0f;   // also zeroes the j=23 pad slot

    const float*  xb      = g_xg + (size_t)batch * GP_;
    const size_t  tstride = (size_t)B_ * GP_;
    float*        ob      = out + (size_t)batch * T_ * H_;

    // Software prefetch pipeline, distance 2
    float xr0 = xb[l],            xz0 = xb[H_ + l],            xn0 = xb[2 * H_ + l];
    const float* p1 = xb + tstride;
    float xr1 = p1[l],            xz1 = p1[H_ + l],            xn1 = p1[2 * H_ + l];

    for (int t = 0; t < T_; t++) {
        const float xr = xr0, xz = xz0, xn = xn0;
        xr0 = xr1; xz0 = xz1; xn0 = xn1;
        const int tn = (t + 2 < T_) ? (t + 2) : (T_ - 1);
        const float* pp = xb + (size_t)tn * tstride;
        xr1 = pp[l]; xz1 = pp[H_ + l]; xn1 = pp[2 * H_ + l];

        // hg = W_hh · h + b_hh  (3 rows, packed pairs over j)
        unsigned long long ar = pack2(bhr, 0.0f);
        unsigned long long az = pack2(bhz, 0.0f);
        unsigned long long an = pack2(bhn, 0.0f);
#pragma unroll
        for (int j = 0; j < 12; j++) {
            ar = ffma2(wr[j], h2[j], ar);
            az = ffma2(wz[j], h2[j], az);
            an = ffma2(wn[j], h2[j], an);
        }
        float hrx, hry, hzx, hzy, hnx, hny;
        unpack2(ar, hrx, hry);
        unpack2(az, hzx, hzy);
        unpack2(an, hnx, hny);

        const float r = fast_sigmoid(xr + (hrx + hry));
        const float z = fast_sigmoid(xz + (hzx + hzy));
        const float n = fast_tanh(fmaf(r, hnx + hny, xn));
        const float hnew = fmaf(z, hmine - n, n);    // (1-z)*n + z*h

        if (act) ob[(size_t)t * H_ + lane] = fmaf(piw, hnew, pib);
        hmine = hnew;

        // Replicate h across lanes for next step
        __syncwarp();                 // prior LDS of all lanes done before overwrite
        if (act) hsh[wb][lane] = hnew;
        __syncwarp();
#pragma unroll
        for (int j = 0; j < 12; j++)
            h2[j] = *reinterpret_cast<const unsigned long long*>(&hsh[wb][2 * j]);
    }

    // hidden = hT
    if (act)
        out[(size_t)B_ * T_ * H_ + (size_t)batch * H_ + lane] = hmine;
}

// ---------------------------------------------------------------------------
extern "C" void kernel_launch(void* const* d_in, const int* in_sizes, int n_in,
                              void* d_out, int out_size)
{
    const float* task = (const float*)d_in[0];   // (2048, 512, 58)
    const float* Wih  = (const float*)d_in[1];   // (69, 58)
    const float* Whh  = (const float*)d_in[2];   // (69, 23)
    const float* bih  = (const float*)d_in[3];   // (69,)
    const float* bhh  = (const float*)d_in[4];   // (69,)
    const float* piw  = (const float*)d_in[5];   // (23,)
    const float* pib  = (const float*)d_in[6];   // (23,)
    float* out = (float*)d_out;                  // action_pred (2048,512,23) ++ hidden (1,2048,23)

    xproj_kernel<<<(B_ * T_) / 256, 256>>>(task, Wih, bih);
    scan_kernel<<<B_ / 4, 128>>>(Whh, bhh, piw, pib, out);
}

// round 3
// speedup vs baseline: 1.0703x; 1.0703x over previous
#include <cuda_runtime.h>

// Problem dims (fixed for this problem instance)
#define B_  2048
#define T_  512
#define I_  58      // input features
#define H_  23      // hidden
#define G_  69      // 3*H gate rows
#define GP_ 72      // padded gate dim (even, 32B-multiple rows)
#define KP_ 64      // padded K for tf32 mma (8 k-frags of 8)

// Scratch for x-projection: [B][T][GP_] fp32 (~302 MB, static device array — no allocs)
// Layout [b][t][g]: xproj writes contiguous rows (m = b*T + t), scan streams sequentially.
__device__ float g_xg[(size_t)B_ * T_ * GP_];

// ---------------------------------------------------------------------------
// Helpers
// ---------------------------------------------------------------------------
__device__ __forceinline__ unsigned cvt_tf32(float f) {
    unsigned u;
    asm("cvt.rna.tf32.f32 %0, %1;" : "=r"(u) : "f"(f));
    return u;
}
__device__ __forceinline__ unsigned long long pack2(float lo, float hi) {
    unsigned long long r;
    asm("mov.b64 %0, {%1, %2};" : "=l"(r) : "f"(lo), "f"(hi));
    return r;
}
__device__ __forceinline__ void unpack2(unsigned long long v, float& lo, float& hi) {
    asm("mov.b64 {%0, %1}, %2;" : "=f"(lo), "=f"(hi) : "l"(v));
}
// Packed dual-FMA (Blackwell f32x2)
__device__ __forceinline__ unsigned long long ffma2(unsigned long long a,
                                                    unsigned long long b,
                                                    unsigned long long c) {
    unsigned long long d;
    asm("fma.rn.f32x2 %0, %1, %2, %3;" : "=l"(d) : "l"(a), "l"(b), "l"(c));
    return d;
}
__device__ __forceinline__ unsigned long long add2(unsigned long long a,
                                                   unsigned long long b) {
    unsigned long long d;
    asm("add.rn.f32x2 %0, %1, %2;" : "=l"(d) : "l"(a), "l"(b));
    return d;
}

// Accurate fast sigmoid/tanh via MUFU.EX2 + MUFU.RCP (~1e-7 rel err)
__device__ __forceinline__ float fast_sigmoid(float x) {
    float e, r;
    asm("ex2.approx.f32 %0, %1;" : "=f"(e) : "f"(x * -1.4426950408889634f));
    asm("rcp.approx.f32 %0, %1;" : "=f"(r) : "f"(e + 1.0f));
    return r;
}
__device__ __forceinline__ float fast_tanh(float x) {
    float e, r;
    asm("ex2.approx.f32 %0, %1;" : "=f"(e) : "f"(x * -2.8853900817779268f));
    asm("rcp.approx.f32 %0, %1;" : "=f"(r) : "f"(e + 1.0f));
    return fmaf(2.0f, r, -1.0f);
}

// ---------------------------------------------------------------------------
// Kernel 1: x-projection GEMM (tf32 mma.sync):
//   xg[b][t][g] = task[b][t]·W_ih^T + b_ih,  row index m = b*T + t (contiguous).
// ---------------------------------------------------------------------------
__global__ void __launch_bounds__(256, 2)
xproj_kernel(const float* __restrict__ task,
             const float* __restrict__ Wih,
             const float* __restrict__ bih)
{
    __shared__ unsigned Bsh[KP_][GP_];   // tf32 bits: Bsh[k][n] = Wih[n][k]
    __shared__ float    bias[GP_];

    const int tid = threadIdx.x;

    for (int idx = tid; idx < KP_ * GP_; idx += 256) {
        int k = idx / GP_, n = idx % GP_;
        float v = (k < I_ && n < G_) ? Wih[n * I_ + k] : 0.0f;
        Bsh[k][n] = cvt_tf32(v);
    }
    if (tid < GP_) bias[tid] = (tid < G_) ? bih[tid] : 0.0f;
    __syncthreads();

    const int warp = tid >> 5;
    const int lane = tid & 31;
    const int qr = lane >> 2;   // groupID (0..7)
    const int qc = lane & 3;    // tid-in-group (0..3)
    const int m_warp = blockIdx.x * 256 + warp * 32;

    float acc[2][9][4];
#pragma unroll
    for (int mt = 0; mt < 2; mt++)
#pragma unroll
        for (int nt = 0; nt < 9; nt++)
#pragma unroll
            for (int i = 0; i < 4; i++) acc[mt][nt][i] = 0.0f;

#pragma unroll
    for (int kf = 0; kf < 8; kf++) {
        const int k0 = kf * 8;
        unsigned bfr[9][2];
#pragma unroll
        for (int nt = 0; nt < 9; nt++) {
            bfr[nt][0] = Bsh[k0 + qc][nt * 8 + qr];
            bfr[nt][1] = Bsh[k0 + qc + 4][nt * 8 + qr];
        }
        const int c0 = k0 + qc;
        const int c1 = c0 + 4;
#pragma unroll
        for (int mt = 0; mt < 2; mt++) {
            const float* arow0 = task + (size_t)(m_warp + mt * 16 + qr) * I_;
            const float* arow1 = arow0 + (size_t)8 * I_;
            unsigned a0 = (c0 < I_) ? cvt_tf32(__ldg(arow0 + c0)) : 0u;
            unsigned a1 = (c0 < I_) ? cvt_tf32(__ldg(arow1 + c0)) : 0u;
            unsigned a2 = (c1 < I_) ? cvt_tf32(__ldg(arow0 + c1)) : 0u;
            unsigned a3 = (c1 < I_) ? cvt_tf32(__ldg(arow1 + c1)) : 0u;
#pragma unroll
            for (int nt = 0; nt < 9; nt++) {
                asm volatile(
                    "mma.sync.aligned.m16n8k8.row.col.f32.tf32.tf32.f32 "
                    "{%0,%1,%2,%3}, {%4,%5,%6,%7}, {%8,%9}, {%0,%1,%2,%3};"
                    : "+f"(acc[mt][nt][0]), "+f"(acc[mt][nt][1]),
                      "+f"(acc[mt][nt][2]), "+f"(acc[mt][nt][3])
                    : "r"(a0), "r"(a1), "r"(a2), "r"(a3),
                      "r"(bfr[nt][0]), "r"(bfr[nt][1]));
            }
        }
    }

    // Epilogue: bias add, write contiguous rows g_xg[m][:]
#pragma unroll
    for (int mt = 0; mt < 2; mt++) {
#pragma unroll
        for (int half = 0; half < 2; half++) {
            const int m = m_warp + mt * 16 + qr + half * 8;
            float* orow = g_xg + (size_t)m * GP_;
#pragma unroll
            for (int nt = 0; nt < 9; nt++) {
                const int n = nt * 8 + qc * 2;
                float2 v;
                v.x = acc[mt][nt][half * 2 + 0] + bias[n];
                v.y = acc[mt][nt][half * 2 + 1] + bias[n + 1];
                *reinterpret_cast<float2*>(orow + n) = v;
            }
        }
    }
}

// ---------------------------------------------------------------------------
// Kernel 2: GRU scan. One warp per batch (2048 one-warp blocks).
//   Lane l<23 owns unit l; W_hh rows in registers as f32x2 pairs.
//   h replicated via double-buffered smem: ONE syncwarp per step.
//   Matvec: 2-way split accumulator chains of fma.rn.f32x2, h read as LDS.128.
// ---------------------------------------------------------------------------
__global__ void __launch_bounds__(32)
scan_kernel(const float* __restrict__ Whh,
            const float* __restrict__ bhh,
            const float* __restrict__ piw_g,
            const float* __restrict__ pib_g,
            float* __restrict__ out)
{
    const int lane  = threadIdx.x;
    const int batch = blockIdx.x;
    const bool act  = lane < H_;
    const int l     = act ? lane : 0;

    __shared__ __align__(16) float hsh[2][24];   // double-buffered h (pad j=23)

    // Pack W_hh rows for this lane: j-pairs (j=23 padded with 0)
    unsigned long long wr[12], wz[12], wn[12];
#pragma unroll
    for (int j = 0; j < 12; j++) {
        const int j0 = 2 * j, j1 = 2 * j + 1;
        float r1 = (j1 < H_) ? Whh[(size_t)l * H_ + j1] : 0.0f;
        float z1 = (j1 < H_) ? Whh[(size_t)(H_ + l) * H_ + j1] : 0.0f;
        float n1 = (j1 < H_) ? Whh[(size_t)(2 * H_ + l) * H_ + j1] : 0.0f;
        wr[j] = pack2(Whh[(size_t)l * H_ + j0], r1);
        wz[j] = pack2(Whh[(size_t)(H_ + l) * H_ + j0], z1);
        wn[j] = pack2(Whh[(size_t)(2 * H_ + l) * H_ + j0], n1);
    }
    const float bhr = bhh[l], bhz = bhh[H_ + l], bhn = bhh[2 * H_ + l];
    const float piw = piw_g[l], pib = pib_g[l];

    ulonglong2 h4[6];      // 24 h values as 6x (f32x2, f32x2)
#pragma unroll
    for (int j = 0; j < 6; j++) { h4[j].x = 0ull; h4[j].y = 0ull; }
    float hmine = 0.0f;
    if (lane < 24) { hsh[0][lane] = 0.0f; hsh[1][lane] = 0.0f; }
    __syncwarp();

    const float* xb = g_xg + (size_t)batch * T_ * GP_;   // stream: +GP_ per step
    float*       op = out + (size_t)batch * T_ * H_ + lane;

    // Prefetch pipeline, distance 2
    float xr0 = xb[l],  xz0 = xb[H_ + l],  xn0 = xb[2 * H_ + l];
    const float* p1 = xb + GP_;
    float xr1 = p1[l],  xz1 = p1[H_ + l],  xn1 = p1[2 * H_ + l];
    const float* pf = xb + 2 * GP_;

    for (int t = 0; t < T_; t++) {
        const float xr = xr0, xz = xz0, xn = xn0;
        xr0 = xr1; xz0 = xz1; xn0 = xn1;
        xr1 = pf[l]; xz1 = pf[H_ + l]; xn1 = pf[2 * H_ + l];
        if (t + 3 < T_) pf += GP_;

        // hg = W_hh · h + b_hh  (3 rows; two 6-deep packed chains each)
        unsigned long long ar0 = pack2(bhr, 0.0f), ar1 = 0ull;
        unsigned long long az0 = pack2(bhz, 0.0f), az1 = 0ull;
        unsigned long long an0 = pack2(bhn, 0.0f), an1 = 0ull;
#pragma unroll
        for (int jj = 0; jj < 3; jj++) {
            ar0 = ffma2(wr[2 * jj],     h4[jj].x, ar0);
            az0 = ffma2(wz[2 * jj],     h4[jj].x, az0);
            an0 = ffma2(wn[2 * jj],     h4[jj].x, an0);
            ar0 = ffma2(wr[2 * jj + 1], h4[jj].y, ar0);
            az0 = ffma2(wz[2 * jj + 1], h4[jj].y, az0);
            an0 = ffma2(wn[2 * jj + 1], h4[jj].y, an0);
        }
#pragma unroll
        for (int jj = 3; jj < 6; jj++) {
            ar1 = ffma2(wr[2 * jj],     h4[jj].x, ar1);
            az1 = ffma2(wz[2 * jj],     h4[jj].x, az1);
            an1 = ffma2(wn[2 * jj],     h4[jj].x, an1);
            ar1 = ffma2(wr[2 * jj + 1], h4[jj].y, ar1);
            az1 = ffma2(wz[2 * jj + 1], h4[jj].y, az1);
            an1 = ffma2(wn[2 * jj + 1], h4[jj].y, an1);
        }
        float hrx, hry, hzx, hzy, hnx, hny;
        unsigned long long ar = add2(ar0, ar1);
        unsigned long long az = add2(az0, az1);
        unsigned long long an = add2(an0, an1);
        unpack2(ar, hrx, hry);
        unpack2(az, hzx, hzy);
        unpack2(an, hnx, hny);

        const float r = fast_sigmoid(xr + (hrx + hry));
        const float z = fast_sigmoid(xz + (hzx + hzy));
        const float n = fast_tanh(fmaf(r, hnx + hny, xn));
        const float hnew = fmaf(z, hmine - n, n);    // (1-z)*n + z*h

        if (act) *op = fmaf(piw, hnew, pib);
        op += H_;
        hmine = hnew;

        // Replicate h: write buf (t&1), one syncwarp, read buf (t&1).
        // The NEXT step's sync orders these reads before the (t+2) overwrite.
        const int pb = t & 1;
        if (act) hsh[pb][lane] = hnew;
        __syncwarp();
#pragma unroll
        for (int j = 0; j < 6; j++)
            h4[j] = *reinterpret_cast<const ulonglong2*>(&hsh[pb][4 * j]);
    }

    // hidden = hT
    if (act)
        out[(size_t)B_ * T_ * H_ + (size_t)batch * H_ + lane] = hmine;
}

// ---------------------------------------------------------------------------
extern "C" void kernel_launch(void* const* d_in, const int* in_sizes, int n_in,
                              void* d_out, int out_size)
{
    const float* task = (const float*)d_in[0];   // (2048, 512, 58)
    const float* Wih  = (const float*)d_in[1];   // (69, 58)
    const float* Whh  = (const float*)d_in[2];   // (69, 23)
    const float* bih  = (const float*)d_in[3];   // (69,)
    const float* bhh  = (const float*)d_in[4];   // (69,)
    const float* piw  = (const float*)d_in[5];   // (23,)
    const float* pib  = (const float*)d_in[6];   // (23,)
    float* out = (float*)d_out;                  // action_pred (2048,512,23) ++ hidden (1,2048,23)

    xproj_kernel<<<(B_ * T_) / 256, 256>>>(task, Wih, bih);
    scan_kernel<<<B_, 32>>>(Whh, bhh, piw, pib, out);
}